// round 2
// baseline (speedup 1.0000x reference)
#include <cuda_runtime.h>
#include <cstdint>

// Problem constants (from reference)
#define NUSERS 100000
#define NITEMS 200000
#define NNODES 300000            // NUSERS + NITEMS
#define DIM 64
#define NNZ_E 1200000
#define NHOPS 3
#define LEVELS 4                 // NHOPS + 1
// fp32(1.0/0.9): exact fp32 value of python 1/(1-0.1)
#define INV_MESS_KEEP 1.1111112f

// Scratch: __device__ globals (the sanctioned no-alloc workaround)
__device__ float g_B[(size_t)NNODES * DIM];   // SpMM accumulator, 76.8 MB
__device__ float g_v[NNZ_E];                  // per-edge scaled values

// ---------------------------------------------------------------------------
// Threefry-2x32 (JAX-compatible), shared host/device
// ---------------------------------------------------------------------------
__host__ __device__ __forceinline__ uint32_t rotl32(uint32_t x, int r) {
#ifdef __CUDA_ARCH__
    return __funnelshift_l(x, x, r);
#else
    return (x << r) | (x >> (32 - r));
#endif
}

__host__ __device__ __forceinline__ void threefry2x32(
    uint32_t k0, uint32_t k1, uint32_t x0, uint32_t x1,
    uint32_t& o0, uint32_t& o1)
{
    uint32_t ks2 = k0 ^ k1 ^ 0x1BD11BDAu;
    x0 += k0; x1 += k1;
#define TF_R(r) { x0 += x1; x1 = rotl32(x1, r); x1 ^= x0; }
    TF_R(13) TF_R(15) TF_R(26) TF_R(6)
    x0 += k1;  x1 += ks2 + 1u;
    TF_R(17) TF_R(29) TF_R(16) TF_R(24)
    x0 += ks2; x1 += k0 + 2u;
    TF_R(13) TF_R(15) TF_R(26) TF_R(6)
    x0 += k0;  x1 += k1 + 3u;
    TF_R(17) TF_R(29) TF_R(16) TF_R(24)
    x0 += k1;  x1 += ks2 + 4u;
    TF_R(13) TF_R(15) TF_R(26) TF_R(6)
    x0 += ks2; x1 += k0 + 5u;
#undef TF_R
    o0 = x0; o1 = x1;
}

// JAX partitionable mode, 32-bit draw for flat index i (i < 2^32):
// bits = y0 ^ y1 of cipher(key, (0, i))
__device__ __forceinline__ uint32_t tf_bits(uint32_t k0, uint32_t k1, uint32_t i) {
    uint32_t a, b;
    threefry2x32(k0, k1, 0u, i, a, b);
    return a ^ b;
}

__device__ __forceinline__ float bits_to_u01(uint32_t bits) {
    // jax.random.uniform [0,1): bitcast((bits>>9)|0x3f800000) - 1
    return __uint_as_float((bits >> 9) | 0x3f800000u) - 1.0f;
}

// ---------------------------------------------------------------------------
// Kernels
// ---------------------------------------------------------------------------

// Write level-0 embeddings to out[n, 0, :] and zero g_B.
// One thread per float4: idx in [0, NNODES*16)
__global__ void __launch_bounds__(256)
k_init(const float* __restrict__ ue, const float* __restrict__ ie,
       float* __restrict__ out)
{
    unsigned idx = blockIdx.x * blockDim.x + threadIdx.x;
    if (idx >= (unsigned)NNODES * 16u) return;
    unsigned n = idx >> 4;       // node
    unsigned q = idx & 15u;      // float4 within row
    float4 val;
    if (n < NUSERS)
        val = *reinterpret_cast<const float4*>(ue + (size_t)n * DIM + q * 4);
    else
        val = *reinterpret_cast<const float4*>(ie + (size_t)(n - NUSERS) * DIM + q * 4);
    *reinterpret_cast<float4*>(out + (size_t)n * (LEVELS * DIM) + q * 4) = val;
    reinterpret_cast<float4*>(g_B)[idx] = make_float4(0.f, 0.f, 0.f, 0.f);
}

// Edge dropout: v[e] = (u_e >= 0.5) ? vals[e]*2 : 0
// (floor(0.5+u)==1 <=> u >= 0.5, exact on the fp32 2^-23 grid)
__global__ void __launch_bounds__(256)
k_edge(const float* __restrict__ vals, uint32_t k0, uint32_t k1)
{
    unsigned e = blockIdx.x * blockDim.x + threadIdx.x;
    if (e >= NNZ_E) return;
    float u = bits_to_u01(tf_bits(k0, k1, e));
    g_v[e] = (u >= 0.5f) ? vals[e] * 2.0f : 0.0f;
}

// SpMM: B[r] += v_e * out[c, hop, :].  16 threads per edge, float4 each.
// 50% of edges are dropped -> early exit halves gather + atomic traffic.
__global__ void __launch_bounds__(256)
k_spmm(const int* __restrict__ rows, const int* __restrict__ cols,
       const float* __restrict__ out, int hop)
{
    unsigned idx = blockIdx.x * blockDim.x + threadIdx.x;
    if (idx >= (unsigned)NNZ_E * 16u) return;
    unsigned e = idx >> 4;
    unsigned q = idx & 15u;
    float w = __ldg(&g_v[e]);
    if (w == 0.0f) return;                 // dropped edge
    int c = __ldg(&cols[e]);
    int r = __ldg(&rows[e]);
    float4 s = *reinterpret_cast<const float4*>(
        out + (size_t)c * (LEVELS * DIM) + (size_t)hop * DIM + q * 4);
    float4 a = make_float4(w * s.x, w * s.y, w * s.z, w * s.w);
    atomicAdd(reinterpret_cast<float4*>(g_B + (size_t)r * DIM + q * 4), a);
}

// Message dropout: out[n, hop+1, d] = (u_j < 0.9) ? B[j]*inv : 0 ; re-zero B.
// 2 elements per thread: two interleaved cipher chains for ILP + float2 I/O.
__global__ void __launch_bounds__(256)
k_mess(float* __restrict__ out, uint32_t k0, uint32_t k1, int hop)
{
    unsigned t = blockIdx.x * blockDim.x + threadIdx.x;
    unsigned j = t * 2u;                       // flat element index (even)
    if (j >= (unsigned)NNODES * DIM) return;

    // two independent ciphers, interleaved by the compiler for ILP
    uint32_t a0, b0, a1, b1;
    threefry2x32(k0, k1, 0u, j,      a0, b0);
    threefry2x32(k0, k1, 0u, j + 1u, a1, b1);
    float u0 = bits_to_u01(a0 ^ b0);
    float u1 = bits_to_u01(a1 ^ b1);

    float2 acc = *reinterpret_cast<const float2*>(g_B + j);
    float2 res;
    res.x = (u0 < 0.9f) ? acc.x * INV_MESS_KEEP : 0.0f;
    res.y = (u1 < 0.9f) ? acc.y * INV_MESS_KEEP : 0.0f;

    unsigned n = j >> 6;                       // DIM == 64
    unsigned d = j & 63u;                      // even, so d, d+1 in same row
    *reinterpret_cast<float2*>(
        out + (size_t)n * (LEVELS * DIM) + (size_t)(hop + 1) * DIM + d) = res;
    *reinterpret_cast<float2*>(g_B + j) = make_float2(0.f, 0.f);  // next hop
}

// ---------------------------------------------------------------------------
// Launch
// ---------------------------------------------------------------------------
extern "C" void kernel_launch(void* const* d_in, const int* in_sizes, int n_in,
                              void* d_out, int out_size)
{
    // Resolve inputs by size (the three NNZ-sized arrays keep dict order:
    // vals, rows, cols).
    const float* ue = nullptr; const float* ie = nullptr;
    const float* vals = nullptr; const int* rows = nullptr; const int* cols = nullptr;
    int nnz_seen = 0;
    for (int i = 0; i < n_in; i++) {
        if (in_sizes[i] == NUSERS * DIM)      ue = (const float*)d_in[i];
        else if (in_sizes[i] == NITEMS * DIM) ie = (const float*)d_in[i];
        else if (in_sizes[i] == NNZ_E) {
            if (nnz_seen == 0)      vals = (const float*)d_in[i];
            else if (nnz_seen == 1) rows = (const int*)d_in[i];
            else                    cols = (const int*)d_in[i];
            nnz_seen++;
        }
    }
    float* out = (float*)d_out;

    // Host-side key derivation (JAX): base = key(42) = (0, 42)
    // hop key = fold_in(base, hop) = cipher(base, (0, hop))
    // split(hk, 2) foldlike: ke = cipher(hk, (0,0)), km = cipher(hk, (0,1))
    uint32_t ke0[NHOPS], ke1[NHOPS], km0[NHOPS], km1[NHOPS];
    for (int h = 0; h < NHOPS; h++) {
        uint32_t h0, h1;
        threefry2x32(0u, 42u, 0u, (uint32_t)h, h0, h1);
        threefry2x32(h0, h1, 0u, 0u, ke0[h], ke1[h]);
        threefry2x32(h0, h1, 0u, 1u, km0[h], km1[h]);
    }

    const int TB = 256;
    unsigned n_init = (unsigned)NNODES * 16u;          // float4 slots
    unsigned n_mess = (unsigned)NNODES * DIM / 2u;     // 2 elems/thread
    unsigned n_spmm = (unsigned)NNZ_E * 16u;

    k_init<<<(n_init + TB - 1) / TB, TB>>>(ue, ie, out);
    for (int h = 0; h < NHOPS; h++) {
        k_edge<<<(NNZ_E + TB - 1) / TB, TB>>>(vals, ke0[h], ke1[h]);
        k_spmm<<<(n_spmm + TB - 1) / TB, TB>>>(rows, cols, out, h);
        k_mess<<<(n_mess + TB - 1) / TB, TB>>>(out, km0[h], km1[h], h);
    }
}

// round 3
// speedup vs baseline: 1.3846x; 1.3846x over previous
#include <cuda_runtime.h>
#include <cstdint>

#define NUSERS 100000
#define NITEMS 200000
#define NNODES 300000
#define DIM 64
#define ROWSTRIDE 256            // LEVELS * DIM
#define NNZ_E 1200000
#define NHOPS 3
#define INV_MESS_KEEP 1.1111112f // fp32(1/0.9)

#define SCAN_BLK 1024
#define NBLK ((NNODES + SCAN_BLK - 1) / SCAN_BLK)   // 293

// Scratch (__device__ globals; no allocation allowed). ~7 MB total.
__device__ unsigned g_deg[NNODES];        // degree histogram, then scatter cursor
__device__ unsigned g_rowptr[NNODES + 1]; // CSR row pointers
__device__ unsigned g_bsum[NBLK];         // scan block sums
__device__ unsigned g_eidx[NNZ_E];        // CSR edge index list
__device__ float    g_v[NNZ_E];           // per-edge dropped+scaled values (per hop)

// ---------------------------------------------------------------------------
// Threefry-2x32 (JAX partitionable mode) — validated bit-exact in round 2
// ---------------------------------------------------------------------------
__host__ __device__ __forceinline__ uint32_t rotl32(uint32_t x, int r) {
#ifdef __CUDA_ARCH__
    return __funnelshift_l(x, x, r);
#else
    return (x << r) | (x >> (32 - r));
#endif
}

__host__ __device__ __forceinline__ void threefry2x32(
    uint32_t k0, uint32_t k1, uint32_t x0, uint32_t x1,
    uint32_t& o0, uint32_t& o1)
{
    uint32_t ks2 = k0 ^ k1 ^ 0x1BD11BDAu;
    x0 += k0; x1 += k1;
#define TF_R(r) { x0 += x1; x1 = rotl32(x1, r); x1 ^= x0; }
    TF_R(13) TF_R(15) TF_R(26) TF_R(6)
    x0 += k1;  x1 += ks2 + 1u;
    TF_R(17) TF_R(29) TF_R(16) TF_R(24)
    x0 += ks2; x1 += k0 + 2u;
    TF_R(13) TF_R(15) TF_R(26) TF_R(6)
    x0 += k0;  x1 += k1 + 3u;
    TF_R(17) TF_R(29) TF_R(16) TF_R(24)
    x0 += k1;  x1 += ks2 + 4u;
    TF_R(13) TF_R(15) TF_R(26) TF_R(6)
    x0 += ks2; x1 += k0 + 5u;
#undef TF_R
    o0 = x0; o1 = x1;
}

__device__ __forceinline__ uint32_t tf_bits(uint32_t k0, uint32_t k1, uint32_t i) {
    uint32_t a, b;
    threefry2x32(k0, k1, 0u, i, a, b);
    return a ^ b;
}

__device__ __forceinline__ float bits_to_u01(uint32_t bits) {
    return __uint_as_float((bits >> 9) | 0x3f800000u) - 1.0f;
}

// ---------------------------------------------------------------------------
// init: write level-0 embeddings to out[n, 0, :], zero degree histogram
// ---------------------------------------------------------------------------
__global__ void __launch_bounds__(256)
k_init(const float* __restrict__ ue, const float* __restrict__ ie,
       float* __restrict__ out)
{
    unsigned idx = blockIdx.x * blockDim.x + threadIdx.x;
    if (idx < NNODES) g_deg[idx] = 0u;
    if (idx >= (unsigned)NNODES * 16u) return;
    unsigned n = idx >> 4;
    unsigned q = idx & 15u;
    float4 val;
    if (n < NUSERS)
        val = *reinterpret_cast<const float4*>(ue + (size_t)n * DIM + q * 4);
    else
        val = *reinterpret_cast<const float4*>(ie + (size_t)(n - NUSERS) * DIM + q * 4);
    *reinterpret_cast<float4*>(out + (size_t)n * ROWSTRIDE + q * 4) = val;
}

// ---------------------------------------------------------------------------
// CSR build: histogram -> 2-level exclusive scan -> scatter
// ---------------------------------------------------------------------------
__global__ void __launch_bounds__(256)
k_hist(const int* __restrict__ rows)
{
    unsigned e = blockIdx.x * blockDim.x + threadIdx.x;
    if (e >= NNZ_E) return;
    atomicAdd(&g_deg[rows[e]], 1u);
}

// per-block exclusive scan over 1024 elems (256 threads x 4)
__global__ void __launch_bounds__(256)
k_scan1()
{
    __shared__ unsigned warp_sums[8];
    unsigned b = blockIdx.x;
    unsigned base = b * SCAN_BLK + threadIdx.x * 4u;
    unsigned v[4];
#pragma unroll
    for (int i = 0; i < 4; i++) {
        unsigned idx = base + i;
        v[i] = (idx < NNODES) ? g_deg[idx] : 0u;
    }
    unsigned tsum = v[0] + v[1] + v[2] + v[3];
    unsigned lane = threadIdx.x & 31u, wid = threadIdx.x >> 5;
    unsigned x = tsum;  // inclusive warp scan
#pragma unroll
    for (int o = 1; o < 32; o <<= 1) {
        unsigned y = __shfl_up_sync(0xFFFFFFFFu, x, o);
        if (lane >= (unsigned)o) x += y;
    }
    if (lane == 31) warp_sums[wid] = x;
    __syncthreads();
    if (wid == 0) {
        unsigned s = (lane < 8) ? warp_sums[lane] : 0u;
#pragma unroll
        for (int o = 1; o < 8; o <<= 1) {
            unsigned y = __shfl_up_sync(0xFFFFFFFFu, s, o);
            if (lane >= (unsigned)o) s += y;
        }
        if (lane < 8) warp_sums[lane] = s;  // inclusive over warps
    }
    __syncthreads();
    unsigned warp_off = (wid > 0) ? warp_sums[wid - 1] : 0u;
    unsigned run = warp_off + (x - tsum);   // thread-exclusive prefix
#pragma unroll
    for (int i = 0; i < 4; i++) {
        unsigned idx = base + i;
        if (idx < NNODES) g_rowptr[idx] = run;
        run += v[i];
    }
    if (threadIdx.x == 255) g_bsum[b] = warp_sums[7];  // block total
}

// single-block exclusive scan of the block sums (NBLK = 293 <= 512)
__global__ void __launch_bounds__(512)
k_scan2()
{
    __shared__ unsigned sm[512];
    unsigned t = threadIdx.x;
    sm[t] = (t < NBLK) ? g_bsum[t] : 0u;
    __syncthreads();
#pragma unroll
    for (int o = 1; o < 512; o <<= 1) {
        unsigned y = (t >= (unsigned)o) ? sm[t - o] : 0u;
        __syncthreads();
        sm[t] += y;
        __syncthreads();
    }
    if (t < NBLK) g_bsum[t] = (t == 0) ? 0u : sm[t - 1];  // exclusive
}

// add block offsets; reset cursor; terminate rowptr
__global__ void __launch_bounds__(256)
k_scan3()
{
    unsigned i = blockIdx.x * blockDim.x + threadIdx.x;
    if (i < NNODES) {
        g_rowptr[i] += g_bsum[i >> 10];
        g_deg[i] = 0u;                     // reuse as scatter cursor
    }
    if (i == 0) g_rowptr[NNODES] = NNZ_E;
}

__global__ void __launch_bounds__(256)
k_scatter(const int* __restrict__ rows)
{
    unsigned e = blockIdx.x * blockDim.x + threadIdx.x;
    if (e >= NNZ_E) return;
    int r = rows[e];
    unsigned pos = g_rowptr[r] + atomicAdd(&g_deg[r], 1u);
    g_eidx[pos] = e;
}

// ---------------------------------------------------------------------------
// edge dropout: v[e] = (u >= 0.5) ? vals[e]*2 : 0
// ---------------------------------------------------------------------------
__global__ void __launch_bounds__(256)
k_edge(const float* __restrict__ vals, uint32_t k0, uint32_t k1)
{
    unsigned e = blockIdx.x * blockDim.x + threadIdx.x;
    if (e >= NNZ_E) return;
    float u = bits_to_u01(tf_bits(k0, k1, e));
    g_v[e] = (u >= 0.5f) ? vals[e] * 2.0f : 0.0f;
}

// ---------------------------------------------------------------------------
// Fused SpMM + message dropout. One warp per row. No atomics, no g_B.
// Each lane owns 2 output floats (float2). RNG for the mask is computed in
// the epilogue and hides under gather latency.
// ---------------------------------------------------------------------------
__global__ void __launch_bounds__(256)
k_spmm_fused(const int* __restrict__ cols, float* __restrict__ out,
             int hop, uint32_t km0, uint32_t km1)
{
    unsigned gw = (blockIdx.x * blockDim.x + threadIdx.x) >> 5;  // global warp = row
    if (gw >= NNODES) return;
    unsigned lane = threadIdx.x & 31u;
    unsigned r = gw;

    unsigned start = g_rowptr[r];
    unsigned end   = g_rowptr[r + 1];

    float2 acc = make_float2(0.f, 0.f);
    const float* src_base = out + (size_t)hop * DIM;

    for (unsigned base = start; base < end; base += 32u) {
        unsigned n = min(32u, end - base);
        float wv = 0.f;
        int   cv = 0;
        if (lane < n) {
            unsigned e = g_eidx[base + lane];
            wv = g_v[e];
            cv = cols[e];
        }
        for (unsigned i = 0; i < n; i++) {
            float wi = __shfl_sync(0xFFFFFFFFu, wv, i);
            int   ci = __shfl_sync(0xFFFFFFFFu, cv, i);
            if (wi != 0.0f) {   // uniform across warp (broadcast)
                float2 s = *reinterpret_cast<const float2*>(
                    src_base + (size_t)ci * ROWSTRIDE + lane * 2u);
                acc.x += wi * s.x;
                acc.y += wi * s.y;
            }
        }
    }

    // message dropout epilogue: element j = r*64 + lane*2
    unsigned j = r * 64u + lane * 2u;
    uint32_t a0, b0, a1, b1;
    threefry2x32(km0, km1, 0u, j,      a0, b0);
    threefry2x32(km0, km1, 0u, j + 1u, a1, b1);
    float u0 = bits_to_u01(a0 ^ b0);
    float u1 = bits_to_u01(a1 ^ b1);

    float2 res;
    res.x = (u0 < 0.9f) ? acc.x * INV_MESS_KEEP : 0.0f;
    res.y = (u1 < 0.9f) ? acc.y * INV_MESS_KEEP : 0.0f;

    *reinterpret_cast<float2*>(
        out + (size_t)r * ROWSTRIDE + (size_t)(hop + 1) * DIM + lane * 2u) = res;
}

// ---------------------------------------------------------------------------
// Launch
// ---------------------------------------------------------------------------
extern "C" void kernel_launch(void* const* d_in, const int* in_sizes, int n_in,
                              void* d_out, int out_size)
{
    const float* ue = nullptr; const float* ie = nullptr;
    const float* vals = nullptr; const int* rows = nullptr; const int* cols = nullptr;
    int nnz_seen = 0;
    for (int i = 0; i < n_in; i++) {
        if (in_sizes[i] == NUSERS * DIM)      ue = (const float*)d_in[i];
        else if (in_sizes[i] == NITEMS * DIM) ie = (const float*)d_in[i];
        else if (in_sizes[i] == NNZ_E) {
            if (nnz_seen == 0)      vals = (const float*)d_in[i];
            else if (nnz_seen == 1) rows = (const int*)d_in[i];
            else                    cols = (const int*)d_in[i];
            nnz_seen++;
        }
    }
    float* out = (float*)d_out;

    // JAX key derivation (validated): base=(0,42); hk=cipher(base,(0,hop));
    // ke=cipher(hk,(0,0)), km=cipher(hk,(0,1))
    uint32_t ke0[NHOPS], ke1[NHOPS], km0[NHOPS], km1[NHOPS];
    for (int h = 0; h < NHOPS; h++) {
        uint32_t h0, h1;
        threefry2x32(0u, 42u, 0u, (uint32_t)h, h0, h1);
        threefry2x32(h0, h1, 0u, 0u, ke0[h], ke1[h]);
        threefry2x32(h0, h1, 0u, 1u, km0[h], km1[h]);
    }

    const int TB = 256;
    unsigned n_init  = (unsigned)NNODES * 16u;
    unsigned n_edge  = NNZ_E;
    unsigned n_fused = (unsigned)NNODES * 32u;   // one warp per row

    k_init<<<(n_init + TB - 1) / TB, TB>>>(ue, ie, out);
    k_hist<<<(n_edge + TB - 1) / TB, TB>>>(rows);
    k_scan1<<<NBLK, TB>>>();
    k_scan2<<<1, 512>>>();
    k_scan3<<<(NNODES + TB - 1) / TB, TB>>>();
    k_scatter<<<(n_edge + TB - 1) / TB, TB>>>(rows);

    for (int h = 0; h < NHOPS; h++) {
        k_edge<<<(n_edge + TB - 1) / TB, TB>>>(vals, ke0[h], ke1[h]);
        k_spmm_fused<<<(n_fused + TB - 1) / TB, TB>>>(cols, out, h, km0[h], km1[h]);
    }
}

// round 4
// speedup vs baseline: 1.4744x; 1.0648x over previous
#include <cuda_runtime.h>
#include <cstdint>

#define NUSERS 100000
#define NITEMS 200000
#define NNODES 300000
#define DIM 64
#define ROWSTRIDE 256            // LEVELS * DIM
#define NNZ_E 1200000
#define NHOPS 3
#define INV_MESS_KEEP 1.1111112f // fp32(1/0.9)

#define SCAN_BLK 1024
#define NBLK ((NNODES + SCAN_BLK - 1) / SCAN_BLK)   // 293

// Scratch (__device__ globals; no allocations allowed). ~25 MB total.
__device__ unsigned g_deg[NNODES];        // degree histogram, then scatter cursor
__device__ unsigned g_rowptr[NNODES + 1]; // CSR row pointers
__device__ unsigned g_bsum[NBLK];         // scan block sums
__device__ unsigned g_eidx[NNZ_E];        // CSR pos -> original edge id (for RNG)
__device__ int      g_cols_csr[NNZ_E];    // CSR-ordered column ids
__device__ float    g_vals_csr[NNZ_E];    // CSR-ordered edge values
__device__ float2   g_ew[NNZ_E];          // per-hop packed {weight, bitcast(col)}

// ---------------------------------------------------------------------------
// Threefry-2x32 (JAX partitionable mode) — validated bit-exact (rel_err 7e-8)
// ---------------------------------------------------------------------------
__host__ __device__ __forceinline__ uint32_t rotl32(uint32_t x, int r) {
#ifdef __CUDA_ARCH__
    return __funnelshift_l(x, x, r);
#else
    return (x << r) | (x >> (32 - r));
#endif
}

__host__ __device__ __forceinline__ void threefry2x32(
    uint32_t k0, uint32_t k1, uint32_t x0, uint32_t x1,
    uint32_t& o0, uint32_t& o1)
{
    uint32_t ks2 = k0 ^ k1 ^ 0x1BD11BDAu;
    x0 += k0; x1 += k1;
#define TF_R(r) { x0 += x1; x1 = rotl32(x1, r); x1 ^= x0; }
    TF_R(13) TF_R(15) TF_R(26) TF_R(6)
    x0 += k1;  x1 += ks2 + 1u;
    TF_R(17) TF_R(29) TF_R(16) TF_R(24)
    x0 += ks2; x1 += k0 + 2u;
    TF_R(13) TF_R(15) TF_R(26) TF_R(6)
    x0 += k0;  x1 += k1 + 3u;
    TF_R(17) TF_R(29) TF_R(16) TF_R(24)
    x0 += k1;  x1 += ks2 + 4u;
    TF_R(13) TF_R(15) TF_R(26) TF_R(6)
    x0 += ks2; x1 += k0 + 5u;
#undef TF_R
    o0 = x0; o1 = x1;
}

__device__ __forceinline__ uint32_t tf_bits(uint32_t k0, uint32_t k1, uint32_t i) {
    uint32_t a, b;
    threefry2x32(k0, k1, 0u, i, a, b);
    return a ^ b;
}

__device__ __forceinline__ float bits_to_u01(uint32_t bits) {
    return __uint_as_float((bits >> 9) | 0x3f800000u) - 1.0f;
}

// ---------------------------------------------------------------------------
// CSR build: zero -> histogram -> 2-level exclusive scan -> scatter(+reorder)
// ---------------------------------------------------------------------------
__global__ void __launch_bounds__(256)
k_zero()
{
    unsigned i = blockIdx.x * blockDim.x + threadIdx.x;
    if (i < NNODES) g_deg[i] = 0u;
}

__global__ void __launch_bounds__(256)
k_hist(const int* __restrict__ rows)
{
    unsigned e = blockIdx.x * blockDim.x + threadIdx.x;
    if (e >= NNZ_E) return;
    atomicAdd(&g_deg[rows[e]], 1u);
}

// per-block exclusive scan over 1024 elems (256 threads x 4)
__global__ void __launch_bounds__(256)
k_scan1()
{
    __shared__ unsigned warp_sums[8];
    unsigned b = blockIdx.x;
    unsigned base = b * SCAN_BLK + threadIdx.x * 4u;
    unsigned v[4];
#pragma unroll
    for (int i = 0; i < 4; i++) {
        unsigned idx = base + i;
        v[i] = (idx < NNODES) ? g_deg[idx] : 0u;
    }
    unsigned tsum = v[0] + v[1] + v[2] + v[3];
    unsigned lane = threadIdx.x & 31u, wid = threadIdx.x >> 5;
    unsigned x = tsum;  // inclusive warp scan
#pragma unroll
    for (int o = 1; o < 32; o <<= 1) {
        unsigned y = __shfl_up_sync(0xFFFFFFFFu, x, o);
        if (lane >= (unsigned)o) x += y;
    }
    if (lane == 31) warp_sums[wid] = x;
    __syncthreads();
    if (wid == 0) {
        unsigned s = (lane < 8) ? warp_sums[lane] : 0u;
#pragma unroll
        for (int o = 1; o < 8; o <<= 1) {
            unsigned y = __shfl_up_sync(0xFFFFFFFFu, s, o);
            if (lane >= (unsigned)o) s += y;
        }
        if (lane < 8) warp_sums[lane] = s;  // inclusive over warps
    }
    __syncthreads();
    unsigned warp_off = (wid > 0) ? warp_sums[wid - 1] : 0u;
    unsigned run = warp_off + (x - tsum);   // thread-exclusive prefix
#pragma unroll
    for (int i = 0; i < 4; i++) {
        unsigned idx = base + i;
        if (idx < NNODES) g_rowptr[idx] = run;
        run += v[i];
    }
    if (threadIdx.x == 255) g_bsum[b] = warp_sums[7];  // block total
}

// single-block exclusive scan of block sums (NBLK = 293 <= 512)
__global__ void __launch_bounds__(512)
k_scan2()
{
    __shared__ unsigned sm[512];
    unsigned t = threadIdx.x;
    sm[t] = (t < NBLK) ? g_bsum[t] : 0u;
    __syncthreads();
#pragma unroll
    for (int o = 1; o < 512; o <<= 1) {
        unsigned y = (t >= (unsigned)o) ? sm[t - o] : 0u;
        __syncthreads();
        sm[t] += y;
        __syncthreads();
    }
    if (t < NBLK) g_bsum[t] = (t == 0) ? 0u : sm[t - 1];  // exclusive
}

__global__ void __launch_bounds__(256)
k_scan3()
{
    unsigned i = blockIdx.x * blockDim.x + threadIdx.x;
    if (i < NNODES) {
        g_rowptr[i] += g_bsum[i >> 10];
        g_deg[i] = 0u;                     // reuse as scatter cursor
    }
    if (i == 0) g_rowptr[NNODES] = NNZ_E;
}

// scatter + reorder edge payloads into CSR order
__global__ void __launch_bounds__(256)
k_scatter(const int* __restrict__ rows, const int* __restrict__ cols,
          const float* __restrict__ vals)
{
    unsigned e = blockIdx.x * blockDim.x + threadIdx.x;
    if (e >= NNZ_E) return;
    int r = rows[e];
    unsigned pos = g_rowptr[r] + atomicAdd(&g_deg[r], 1u);
    g_eidx[pos]     = e;
    g_cols_csr[pos] = cols[e];
    g_vals_csr[pos] = vals[e];
}

// ---------------------------------------------------------------------------
// Per-hop edge dropout, streaming in CSR order; packs {w, col} into 8 bytes.
// ---------------------------------------------------------------------------
__global__ void __launch_bounds__(256)
k_edge(uint32_t k0, uint32_t k1)
{
    unsigned p = blockIdx.x * blockDim.x + threadIdx.x;
    if (p >= NNZ_E) return;
    unsigned e = g_eidx[p];
    float u = bits_to_u01(tf_bits(k0, k1, e));
    float w = (u >= 0.5f) ? g_vals_csr[p] * 2.0f : 0.0f;
    g_ew[p] = make_float2(w, __int_as_float(g_cols_csr[p]));
}

// ---------------------------------------------------------------------------
// Fused SpMM + message dropout. One warp per row, float2 per lane.
// Edge payload read as one 8B broadcast load (no shuffles).
// HOP0 gathers straight from ue/ie and also emits the level-0 copy.
// ---------------------------------------------------------------------------
template <bool HOP0>
__global__ void __launch_bounds__(256)
k_spmm_fused(const float* __restrict__ ue, const float* __restrict__ ie,
             float* __restrict__ out, int hop, uint32_t km0, uint32_t km1)
{
    unsigned r = (blockIdx.x * blockDim.x + threadIdx.x) >> 5;  // row
    if (r >= NNODES) return;
    unsigned lane = threadIdx.x & 31u;

    unsigned start = g_rowptr[r];
    unsigned end   = g_rowptr[r + 1];

    float2 acc = make_float2(0.f, 0.f);
    const float* src_base = out + (size_t)hop * DIM;   // used when !HOP0

    auto gather = [&](float w, int c) {
        const float* srow;
        if (HOP0)
            srow = (c < NUSERS) ? (ue + (size_t)c * DIM)
                                : (ie + (size_t)(c - NUSERS) * DIM);
        else
            srow = src_base + (size_t)c * ROWSTRIDE;
        float2 s = *reinterpret_cast<const float2*>(srow + lane * 2u);
        acc.x += w * s.x;
        acc.y += w * s.y;
    };

    unsigned p = start;
    for (; p + 2u <= end; p += 2u) {
        float2 ew0 = g_ew[p];        // broadcast: all lanes same address
        float2 ew1 = g_ew[p + 1u];
        if (ew0.x != 0.0f) gather(ew0.x, __float_as_int(ew0.y));
        if (ew1.x != 0.0f) gather(ew1.x, __float_as_int(ew1.y));
    }
    if (p < end) {
        float2 ew = g_ew[p];
        if (ew.x != 0.0f) gather(ew.x, __float_as_int(ew.y));
    }

    // message dropout epilogue: element j = r*64 + lane*2
    unsigned j = r * 64u + lane * 2u;
    uint32_t a0, b0, a1, b1;
    threefry2x32(km0, km1, 0u, j,      a0, b0);
    threefry2x32(km0, km1, 0u, j + 1u, a1, b1);
    float u0 = bits_to_u01(a0 ^ b0);
    float u1 = bits_to_u01(a1 ^ b1);

    float2 res;
    res.x = (u0 < 0.9f) ? acc.x * INV_MESS_KEEP : 0.0f;
    res.y = (u1 < 0.9f) ? acc.y * INV_MESS_KEEP : 0.0f;

    float* orow = out + (size_t)r * ROWSTRIDE;
    *reinterpret_cast<float2*>(orow + (size_t)(hop + 1) * DIM + lane * 2u) = res;

    if (HOP0) {
        // emit level-0 copy (row r of concat(ue, ie)); rows are L2-hot
        const float* erow = (r < NUSERS) ? (ue + (size_t)r * DIM)
                                         : (ie + (size_t)(r - NUSERS) * DIM);
        float2 e0 = *reinterpret_cast<const float2*>(erow + lane * 2u);
        *reinterpret_cast<float2*>(orow + lane * 2u) = e0;
    }
}

// ---------------------------------------------------------------------------
// Launch
// ---------------------------------------------------------------------------
extern "C" void kernel_launch(void* const* d_in, const int* in_sizes, int n_in,
                              void* d_out, int out_size)
{
    const float* ue = nullptr; const float* ie = nullptr;
    const float* vals = nullptr; const int* rows = nullptr; const int* cols = nullptr;
    int nnz_seen = 0;
    for (int i = 0; i < n_in; i++) {
        if (in_sizes[i] == NUSERS * DIM)      ue = (const float*)d_in[i];
        else if (in_sizes[i] == NITEMS * DIM) ie = (const float*)d_in[i];
        else if (in_sizes[i] == NNZ_E) {
            if (nnz_seen == 0)      vals = (const float*)d_in[i];
            else if (nnz_seen == 1) rows = (const int*)d_in[i];
            else                    cols = (const int*)d_in[i];
            nnz_seen++;
        }
    }
    float* out = (float*)d_out;

    // JAX key derivation (validated): base=(0,42); hk=cipher(base,(0,hop));
    // ke=cipher(hk,(0,0)), km=cipher(hk,(0,1))
    uint32_t ke0[NHOPS], ke1[NHOPS], km0[NHOPS], km1[NHOPS];
    for (int h = 0; h < NHOPS; h++) {
        uint32_t h0, h1;
        threefry2x32(0u, 42u, 0u, (uint32_t)h, h0, h1);
        threefry2x32(h0, h1, 0u, 0u, ke0[h], ke1[h]);
        threefry2x32(h0, h1, 0u, 1u, km0[h], km1[h]);
    }

    const int TB = 256;
    unsigned gb_node = (NNODES + TB - 1) / TB;
    unsigned gb_edge = (NNZ_E + TB - 1) / TB;
    unsigned gb_fuse = ((unsigned)NNODES * 32u + TB - 1) / TB;

    k_zero<<<gb_node, TB>>>();
    k_hist<<<gb_edge, TB>>>(rows);
    k_scan1<<<NBLK, TB>>>();
    k_scan2<<<1, 512>>>();
    k_scan3<<<gb_node, TB>>>();
    k_scatter<<<gb_edge, TB>>>(rows, cols, vals);

    for (int h = 0; h < NHOPS; h++) {
        k_edge<<<gb_edge, TB>>>(ke0[h], ke1[h]);
        if (h == 0)
            k_spmm_fused<true><<<gb_fuse, TB>>>(ue, ie, out, h, km0[h], km1[h]);
        else
            k_spmm_fused<false><<<gb_fuse, TB>>>(ue, ie, out, h, km0[h], km1[h]);
    }
}